// round 15
// baseline (speedup 1.0000x reference)
#include <cuda_runtime.h>
#include <cuda_fp16.h>
#include <cstdint>
#include <cstddef>

// Problem dims
#define M_DIM 8192
#define N_DIM 4096
#define K_DIM 4096

// GEMM tiling: 128x64 CTA tile, 4 warps of 64x32, BK=32, 3-stage ring, 4 CTA/SM
#define BM 128
#define BN 64
#define BK 32
#define NSTAGE 3
#define LDS 40   // halves per smem row (32 + 8 pad -> ldmatrix conflict-free)

#define A_STAGE_HALVES (BM * LDS)   // 5120
#define B_STAGE_HALVES (BN * LDS)   // 2560
#define STAGE_HALVES   (A_STAGE_HALVES + B_STAGE_HALVES)          // 7680
#define SMEM_GEMM_BYTES (NSTAGE * STAGE_HALVES * 2)               // 46080

// ---------------- scratch (no runtime allocation allowed) ----------------
__device__ __align__(16) __half g_wq[(size_t)N_DIM * K_DIM];   // 32 MB
__device__ __align__(16) __half g_xh[(size_t)M_DIM * K_DIM];   // 64 MB
__device__ float g_partial[16384];
__device__ float g_scale;   // c = clip(round(gamma'), -1, 1), in {0, 1}

// ---------------- phase 1: fused prep ----------------
__global__ void prep_all_kernel(const float* __restrict__ w, const float* __restrict__ x) {
    if (blockIdx.x < 16384) {
        __shared__ float sred[256];
        size_t i = (size_t)blockIdx.x * blockDim.x + threadIdx.x;   // one float4
        float4 v = reinterpret_cast<const float4*>(w)[i];

        float q0 = (v.x > 0.5f) ? 1.f : ((v.x < -0.5f) ? -1.f : 0.f);
        float q1 = (v.y > 0.5f) ? 1.f : ((v.y < -0.5f) ? -1.f : 0.f);
        float q2 = (v.z > 0.5f) ? 1.f : ((v.z < -0.5f) ? -1.f : 0.f);
        float q3 = (v.w > 0.5f) ? 1.f : ((v.w < -0.5f) ? -1.f : 0.f);
        __half2* dst = reinterpret_cast<__half2*>(g_wq) + 2 * i;
        dst[0] = __floats2half2_rn(q0, q1);
        dst[1] = __floats2half2_rn(q2, q3);

        float acc = fabsf(v.x) + fabsf(v.y) + fabsf(v.z) + fabsf(v.w);
        sred[threadIdx.x] = acc;
        __syncthreads();
        for (int s = 128; s > 0; s >>= 1) {
            if (threadIdx.x < s) sred[threadIdx.x] += sred[threadIdx.x + s];
            __syncthreads();
        }
        if (threadIdx.x == 0) g_partial[blockIdx.x] = sred[0];
    } else {
        size_t i = (size_t)(blockIdx.x - 16384) * blockDim.x + threadIdx.x;
        float4 v = reinterpret_cast<const float4*>(x)[i];
        __half2* dst = reinterpret_cast<__half2*>(g_xh) + 2 * i;
        dst[0] = __floats2half2_rn(v.x, v.y);
        dst[1] = __floats2half2_rn(v.z, v.w);
    }
}

// ---------------- phase 2: finalize gamma -> scale c ----------------
__global__ void finalize_gamma_kernel() {
    __shared__ float sred[1024];
    int t = threadIdx.x;
    float acc = 0.f;
    #pragma unroll
    for (int k = 0; k < 16; k++) acc += g_partial[t + k * 1024];
    sred[t] = acc;
    __syncthreads();
    for (int s = 512; s > 0; s >>= 1) {
        if (t < s) sred[t] += sred[t + s];
        __syncthreads();
    }
    if (t == 0) {
        float mean = sred[0] / 16777216.0f;
        float gamma = 1.0f / (mean + 1e-7f);
        // wq = clip(round(gamma * q), -1, 1) = q * c with c = min(round(gamma), 1)
        g_scale = fminf(rintf(gamma), 1.0f);
    }
}

// ---------------- phase 3: conditional rescale of g_wq ----------------
__global__ void fix_scale_kernel() {
    const float c = g_scale;
    if (c == 1.0f) return;
    const __half2 ch = __floats2half2_rn(c, c);
    __half2* p = reinterpret_cast<__half2*>(g_wq);
    const size_t n = (size_t)N_DIM * K_DIM / 2;
    for (size_t i = (size_t)blockIdx.x * blockDim.x + threadIdx.x; i < n;
         i += (size_t)gridDim.x * blockDim.x)
        p[i] = __hmul2(p[i], ch);
}

// ---------------- GEMM helpers ----------------
__device__ __forceinline__ uint32_t smem_u32(const void* p) {
    return static_cast<uint32_t>(__cvta_generic_to_shared(p));
}
__device__ __forceinline__ void cp_async16(uint32_t dst, const void* src) {
    asm volatile("cp.async.cg.shared.global [%0], [%1], 16;\n" :: "r"(dst), "l"(src) : "memory");
}
__device__ __forceinline__ void ldm_x4(uint32_t addr, uint32_t& r0, uint32_t& r1, uint32_t& r2, uint32_t& r3) {
    asm volatile("ldmatrix.sync.aligned.m8n8.x4.shared.b16 {%0,%1,%2,%3}, [%4];"
                 : "=r"(r0), "=r"(r1), "=r"(r2), "=r"(r3) : "r"(addr));
}
__device__ __forceinline__ void mma16816(float* c, const uint32_t* a, uint32_t b0, uint32_t b1) {
    asm volatile("mma.sync.aligned.m16n8k16.row.col.f32.f16.f16.f32 "
                 "{%0,%1,%2,%3}, {%4,%5,%6,%7}, {%8,%9}, {%0,%1,%2,%3};"
                 : "+f"(c[0]), "+f"(c[1]), "+f"(c[2]), "+f"(c[3])
                 : "r"(a[0]), "r"(a[1]), "r"(a[2]), "r"(a[3]), "r"(b0), "r"(b1));
}

// one stage: A tile 128x32 + B tile 64x32 (fp16, 16B chunks), 128 threads
__device__ __forceinline__ void load_stage(__half* Asm, __half* Bsm,
                                           const __half* Ag, const __half* Bg,
                                           int kbase, int tid) {
    #pragma unroll
    for (int j = 0; j < 4; j++) {
        int c = tid + j * 128;
        int row = c >> 2, col = (c & 3) * 8;
        cp_async16(smem_u32(Asm + row * LDS + col), Ag + (size_t)row * K_DIM + kbase + col);
    }
    #pragma unroll
    for (int j = 0; j < 2; j++) {
        int c = tid + j * 128;
        int row = c >> 2, col = (c & 3) * 8;
        cp_async16(smem_u32(Bsm + row * LDS + col), Bg + (size_t)row * K_DIM + kbase + col);
    }
    asm volatile("cp.async.commit_group;\n" ::: "memory");
}

// ---------------- phase 4: fp16 tensor-core GEMM, out = Xh @ Wq^T ----------------
__global__ void __launch_bounds__(128, 4) gemm_kernel(float* __restrict__ out) {
    extern __shared__ __half smem[];
    __half* As[NSTAGE];
    __half* Bs[NSTAGE];
    #pragma unroll
    for (int s = 0; s < NSTAGE; s++) {
        As[s] = smem + s * STAGE_HALVES;
        Bs[s] = As[s] + A_STAGE_HALVES;
    }

    const int tid  = threadIdx.x;
    const int lane = tid & 31;
    const int warp = tid >> 5;
    const int wm = (warp & 1) * 64;   // warp tile 64x32
    const int wn = (warp >> 1) * 32;
    const int m0 = blockIdx.y * BM;
    const int n0 = blockIdx.x * BN;

    const __half* Ag = g_xh + (size_t)m0 * K_DIM;
    const __half* Bg = g_wq + (size_t)n0 * K_DIM;

    float acc[4][4][4];
    #pragma unroll
    for (int a = 0; a < 4; a++)
        #pragma unroll
        for (int b = 0; b < 4; b++)
            #pragma unroll
            for (int c = 0; c < 4; c++) acc[a][b][c] = 0.f;

    // prologue: fill NSTAGE-1 stages
    #pragma unroll
    for (int s = 0; s < NSTAGE - 1; s++)
        load_stage(As[s], Bs[s], Ag, Bg, s * BK, tid);

    const int NT = K_DIM / BK;   // 128
    const int arow = (lane & 15);
    const int acol = (lane >> 4) << 3;

    int sidx = 0;
    for (int kt = 0; kt < NT; ++kt) {
        asm volatile("cp.async.wait_group %0;\n" :: "n"(NSTAGE - 2) : "memory");
        __syncthreads();

        const __half* Ab = As[sidx];
        const __half* Bb = Bs[sidx];

        #pragma unroll
        for (int kk = 0; kk < BK; kk += 16) {
            uint32_t a[4][4], b[2][4];
            #pragma unroll
            for (int im = 0; im < 4; im++) {
                uint32_t addr = smem_u32(&Ab[(wm + im * 16 + arow) * LDS + kk + acol]);
                ldm_x4(addr, a[im][0], a[im][1], a[im][2], a[im][3]);
            }
            #pragma unroll
            for (int ib = 0; ib < 2; ib++) {
                uint32_t addr = smem_u32(&Bb[(wn + ib * 16 + arow) * LDS + kk + acol]);
                ldm_x4(addr, b[ib][0], b[ib][1], b[ib][2], b[ib][3]);
            }
            #pragma unroll
            for (int im = 0; im < 4; im++)
                #pragma unroll
                for (int in = 0; in < 4; in++)
                    mma16816(acc[im][in], a[im], b[in >> 1][in & 1], b[in >> 1][(in & 1) + 2]);
        }

        // prefetch stage kt+NSTAGE-1 (buffer freed at kt-1). When past the end,
        // commit an EMPTY group so the wait_group(NSTAGE-2) invariant — "the
        // group for the buffer being consumed is never the newest pending
        // group" — holds through the drain iterations. Without this, the final
        // iteration may read its tile before the cp.async lands (latent race
        // that fired in R14).
        if (kt + NSTAGE - 1 < NT) {
            int ps = sidx + (NSTAGE - 1);
            if (ps >= NSTAGE) ps -= NSTAGE;
            load_stage(As[ps], Bs[ps], Ag, Bg, (kt + NSTAGE - 1) * BK, tid);
        } else {
            asm volatile("cp.async.commit_group;\n" ::: "memory");
        }
        if (++sidx == NSTAGE) sidx = 0;
    }

    // epilogue: fp32 store
    #pragma unroll
    for (int im = 0; im < 4; im++) {
        int r = m0 + wm + im * 16 + (lane >> 2);
        #pragma unroll
        for (int in = 0; in < 4; in++) {
            int c = n0 + wn + in * 8 + (lane & 3) * 2;
            *reinterpret_cast<float2*>(&out[(size_t)r * N_DIM + c]) =
                make_float2(acc[im][in][0], acc[im][in][1]);
            *reinterpret_cast<float2*>(&out[(size_t)(r + 8) * N_DIM + c]) =
                make_float2(acc[im][in][2], acc[im][in][3]);
        }
    }
}

// ---------------- launch ----------------
extern "C" void kernel_launch(void* const* d_in, const int* in_sizes, int n_in,
                              void* d_out, int out_size) {
    const float* x = (const float*)d_in[0];   // 4*2048*4096 fp32
    const float* w = (const float*)d_in[1];   // 4096*4096 fp32
    float* out = (float*)d_out;               // 4*2048*4096 fp32

    cudaFuncSetAttribute(gemm_kernel,
                         cudaFuncAttributeMaxDynamicSharedMemorySize, SMEM_GEMM_BYTES);

    prep_all_kernel<<<49152, 256>>>(w, x);       // launch 0
    finalize_gamma_kernel<<<1, 1024>>>();        // launch 1
    fix_scale_kernel<<<2048, 256>>>();           // launch 2 (no-op when c == 1)
    gemm_kernel<<<dim3(N_DIM / BN, M_DIM / BM), 128, SMEM_GEMM_BYTES>>>(out);  // launch 3
}

// round 16
// speedup vs baseline: 1.1011x; 1.1011x over previous
#include <cuda_runtime.h>
#include <cuda_fp16.h>
#include <cstdint>
#include <cstddef>

// Problem dims
#define M_DIM 8192
#define N_DIM 4096
#define K_DIM 4096

// GEMM tiling (best config, R6/R13): 128x128 CTA, 8 warps of 64x32, BK=64,
// 3-stage cp.async ring, 2 CTA/SM
#define BM 128
#define BN 128
#define BK 64
#define NSTAGE 3
#define LDS 72   // halves per smem row (64 + 8 pad -> ldmatrix conflict-free)

#define A_STAGE_HALVES (BM * LDS)   // 9216
#define B_STAGE_HALVES (BN * LDS)   // 9216
#define STAGE_HALVES   (A_STAGE_HALVES + B_STAGE_HALVES)          // 18432
#define SMEM_GEMM_BYTES (NSTAGE * STAGE_HALVES * 2)               // 110592

// ---------------- scratch (no runtime allocation allowed) ----------------
__device__ __align__(16) __half g_wq[(size_t)N_DIM * K_DIM];   // 32 MB
__device__ __align__(16) __half g_xh[(size_t)M_DIM * K_DIM];   // 64 MB
__device__ float g_partial[16384];
__device__ float g_scale;   // c = clip(round(gamma'), -1, 1), in {0, 1}

// ---------------- phase 1: fused prep ----------------
// blocks [0, 16384):      W pass — extract q in {-1,0,1} to g_wq (fp16) AND
//                         accumulate per-block sum(|W|) partials (one read of W)
// blocks [16384, 49152):  x fp32 -> fp16 convert
__global__ void prep_all_kernel(const float* __restrict__ w, const float* __restrict__ x) {
    if (blockIdx.x < 16384) {
        __shared__ float sred[256];
        size_t i = (size_t)blockIdx.x * blockDim.x + threadIdx.x;   // one float4
        float4 v = reinterpret_cast<const float4*>(w)[i];

        float q0 = (v.x > 0.5f) ? 1.f : ((v.x < -0.5f) ? -1.f : 0.f);
        float q1 = (v.y > 0.5f) ? 1.f : ((v.y < -0.5f) ? -1.f : 0.f);
        float q2 = (v.z > 0.5f) ? 1.f : ((v.z < -0.5f) ? -1.f : 0.f);
        float q3 = (v.w > 0.5f) ? 1.f : ((v.w < -0.5f) ? -1.f : 0.f);
        __half2* dst = reinterpret_cast<__half2*>(g_wq) + 2 * i;
        dst[0] = __floats2half2_rn(q0, q1);
        dst[1] = __floats2half2_rn(q2, q3);

        float acc = fabsf(v.x) + fabsf(v.y) + fabsf(v.z) + fabsf(v.w);
        sred[threadIdx.x] = acc;
        __syncthreads();
        for (int s = 128; s > 0; s >>= 1) {
            if (threadIdx.x < s) sred[threadIdx.x] += sred[threadIdx.x + s];
            __syncthreads();
        }
        if (threadIdx.x == 0) g_partial[blockIdx.x] = sred[0];
    } else {
        size_t i = (size_t)(blockIdx.x - 16384) * blockDim.x + threadIdx.x;
        float4 v = reinterpret_cast<const float4*>(x)[i];
        __half2* dst = reinterpret_cast<__half2*>(g_xh) + 2 * i;
        dst[0] = __floats2half2_rn(v.x, v.y);
        dst[1] = __floats2half2_rn(v.z, v.w);
    }
}

// ---------------- phase 2: finalize gamma -> scale c ----------------
__global__ void finalize_gamma_kernel() {
    __shared__ float sred[1024];
    int t = threadIdx.x;
    float acc = 0.f;
    #pragma unroll
    for (int k = 0; k < 16; k++) acc += g_partial[t + k * 1024];
    sred[t] = acc;
    __syncthreads();
    for (int s = 512; s > 0; s >>= 1) {
        if (t < s) sred[t] += sred[t + s];
        __syncthreads();
    }
    if (t == 0) {
        float mean = sred[0] / 16777216.0f;
        float gamma = 1.0f / (mean + 1e-7f);
        // wq = clip(round(gamma * q), -1, 1) = q * c with c = min(round(gamma), 1)
        // (gamma > 0 always; rintf = round half-to-even matches jnp.round)
        g_scale = fminf(rintf(gamma), 1.0f);
    }
}

// ---------------- phase 3: conditional rescale of g_wq ----------------
// For typical inputs c == 1 and this exits immediately; correct for any input.
__global__ void fix_scale_kernel() {
    const float c = g_scale;
    if (c == 1.0f) return;
    const __half2 ch = __floats2half2_rn(c, c);
    __half2* p = reinterpret_cast<__half2*>(g_wq);
    const size_t n = (size_t)N_DIM * K_DIM / 2;
    for (size_t i = (size_t)blockIdx.x * blockDim.x + threadIdx.x; i < n;
         i += (size_t)gridDim.x * blockDim.x)
        p[i] = __hmul2(p[i], ch);
}

// ---------------- GEMM helpers ----------------
__device__ __forceinline__ uint32_t smem_u32(const void* p) {
    return static_cast<uint32_t>(__cvta_generic_to_shared(p));
}
__device__ __forceinline__ void cp_async16(uint32_t dst, const void* src) {
    asm volatile("cp.async.cg.shared.global [%0], [%1], 16;\n" :: "r"(dst), "l"(src) : "memory");
}
__device__ __forceinline__ void ldm_x4(uint32_t addr, uint32_t& r0, uint32_t& r1, uint32_t& r2, uint32_t& r3) {
    asm volatile("ldmatrix.sync.aligned.m8n8.x4.shared.b16 {%0,%1,%2,%3}, [%4];"
                 : "=r"(r0), "=r"(r1), "=r"(r2), "=r"(r3) : "r"(addr));
}
__device__ __forceinline__ void mma16816(float* c, const uint32_t* a, uint32_t b0, uint32_t b1) {
    asm volatile("mma.sync.aligned.m16n8k16.row.col.f32.f16.f16.f32 "
                 "{%0,%1,%2,%3}, {%4,%5,%6,%7}, {%8,%9}, {%0,%1,%2,%3};"
                 : "+f"(c[0]), "+f"(c[1]), "+f"(c[2]), "+f"(c[3])
                 : "r"(a[0]), "r"(a[1]), "r"(a[2]), "r"(a[3]), "r"(b0), "r"(b1));
}

// one stage: A tile 128x64 + B tile 128x64 (fp16, 16B chunks), 256 threads
__device__ __forceinline__ void load_stage(__half* Asm, __half* Bsm,
                                           const __half* Ag, const __half* Bg,
                                           int kbase, int tid) {
    #pragma unroll
    for (int j = 0; j < 4; j++) {
        int c = tid + j * 256;
        int row = c >> 3, col = (c & 7) * 8;
        cp_async16(smem_u32(Asm + row * LDS + col), Ag + (size_t)row * K_DIM + kbase + col);
    }
    #pragma unroll
    for (int j = 0; j < 4; j++) {
        int c = tid + j * 256;
        int row = c >> 3, col = (c & 7) * 8;
        cp_async16(smem_u32(Bsm + row * LDS + col), Bg + (size_t)row * K_DIM + kbase + col);
    }
    asm volatile("cp.async.commit_group;\n" ::: "memory");
}

// ---------------- phase 4: fp16 tensor-core GEMM, out = Xh @ Wq^T ----------------
__global__ void __launch_bounds__(256, 2) gemm_kernel(float* __restrict__ out) {
    extern __shared__ __half smem[];
    __half* As[NSTAGE];
    __half* Bs[NSTAGE];
    #pragma unroll
    for (int s = 0; s < NSTAGE; s++) {
        As[s] = smem + s * STAGE_HALVES;
        Bs[s] = As[s] + A_STAGE_HALVES;
    }

    const int tid  = threadIdx.x;
    const int lane = tid & 31;
    const int warp = tid >> 5;
    const int wm = (warp & 1) * 64;   // warp tile 64x32
    const int wn = (warp >> 1) * 32;
    const int m0 = blockIdx.y * BM;
    const int n0 = blockIdx.x * BN;

    const __half* Ag = g_xh + (size_t)m0 * K_DIM;
    const __half* Bg = g_wq + (size_t)n0 * K_DIM;

    float acc[4][4][4];
    #pragma unroll
    for (int a = 0; a < 4; a++)
        #pragma unroll
        for (int b = 0; b < 4; b++)
            #pragma unroll
            for (int c = 0; c < 4; c++) acc[a][b][c] = 0.f;

    // prologue: fill NSTAGE-1 stages
    #pragma unroll
    for (int s = 0; s < NSTAGE - 1; s++)
        load_stage(As[s], Bs[s], Ag, Bg, s * BK, tid);

    const int NT = K_DIM / BK;   // 64
    const int arow = (lane & 15);
    const int acol = (lane >> 4) << 3;

    int sidx = 0;
    for (int kt = 0; kt < NT; ++kt) {
        asm volatile("cp.async.wait_group %0;\n" :: "n"(NSTAGE - 2) : "memory");
        __syncthreads();

        const __half* Ab = As[sidx];
        const __half* Bb = Bs[sidx];

        #pragma unroll
        for (int kk = 0; kk < BK; kk += 16) {
            uint32_t a[4][4], b[2][4];
            #pragma unroll
            for (int im = 0; im < 4; im++) {
                uint32_t addr = smem_u32(&Ab[(wm + im * 16 + arow) * LDS + kk + acol]);
                ldm_x4(addr, a[im][0], a[im][1], a[im][2], a[im][3]);
            }
            #pragma unroll
            for (int ib = 0; ib < 2; ib++) {
                uint32_t addr = smem_u32(&Bb[(wn + ib * 16 + arow) * LDS + kk + acol]);
                ldm_x4(addr, b[ib][0], b[ib][1], b[ib][2], b[ib][3]);
            }
            #pragma unroll
            for (int im = 0; im < 4; im++)
                #pragma unroll
                for (int in = 0; in < 4; in++)
                    mma16816(acc[im][in], a[im], b[in >> 1][in & 1], b[in >> 1][(in & 1) + 2]);
        }

        // prefetch stage kt+NSTAGE-1 (buffer freed at kt-1). When past the end,
        // commit an EMPTY group so the wait_group(NSTAGE-2) invariant — "the
        // group for the buffer being consumed is never the newest pending
        // group" — holds through the drain iterations. Without this, the final
        // iterations may read their tile before the cp.async lands (latent
        // race that fired in R14).
        if (kt + NSTAGE - 1 < NT) {
            int ps = sidx + (NSTAGE - 1);
            if (ps >= NSTAGE) ps -= NSTAGE;
            load_stage(As[ps], Bs[ps], Ag, Bg, (kt + NSTAGE - 1) * BK, tid);
        } else {
            asm volatile("cp.async.commit_group;\n" ::: "memory");
        }
        if (++sidx == NSTAGE) sidx = 0;
    }

    // epilogue: fp32 store
    #pragma unroll
    for (int im = 0; im < 4; im++) {
        int r = m0 + wm + im * 16 + (lane >> 2);
        #pragma unroll
        for (int in = 0; in < 4; in++) {
            int c = n0 + wn + in * 8 + (lane & 3) * 2;
            *reinterpret_cast<float2*>(&out[(size_t)r * N_DIM + c]) =
                make_float2(acc[im][in][0], acc[im][in][1]);
            *reinterpret_cast<float2*>(&out[(size_t)(r + 8) * N_DIM + c]) =
                make_float2(acc[im][in][2], acc[im][in][3]);
        }
    }
}

// ---------------- launch ----------------
extern "C" void kernel_launch(void* const* d_in, const int* in_sizes, int n_in,
                              void* d_out, int out_size) {
    const float* x = (const float*)d_in[0];   // 4*2048*4096 fp32
    const float* w = (const float*)d_in[1];   // 4096*4096 fp32
    float* out = (float*)d_out;               // 4*2048*4096 fp32

    cudaFuncSetAttribute(gemm_kernel,
                         cudaFuncAttributeMaxDynamicSharedMemorySize, SMEM_GEMM_BYTES);

    prep_all_kernel<<<49152, 256>>>(w, x);       // launch 0: q-extract + |W| partials + x convert
    finalize_gamma_kernel<<<1, 1024>>>();        // launch 1: gamma -> c
    fix_scale_kernel<<<2048, 256>>>();           // launch 2: no-op when c == 1
    gemm_kernel<<<dim3(N_DIM / BN, M_DIM / BM), 256, SMEM_GEMM_BYTES>>>(out);  // launch 3
}

// round 17
// speedup vs baseline: 1.1215x; 1.0185x over previous
#include <cuda_runtime.h>
#include <cuda_fp16.h>
#include <cstdint>
#include <cstddef>

// Problem dims
#define M_DIM 8192
#define N_DIM 4096
#define K_DIM 4096

// GEMM tiling (best config, R6/R13/R16): 128x128 CTA, 8 warps of 64x32, BK=64,
// 3-stage cp.async ring, 2 CTA/SM
#define BM 128
#define BN 128
#define BK 64
#define NSTAGE 3
#define LDS 72   // halves per smem row (64 + 8 pad -> ldmatrix conflict-free)

#define A_STAGE_HALVES (BM * LDS)   // 9216
#define B_STAGE_HALVES (BN * LDS)   // 9216
#define STAGE_HALVES   (A_STAGE_HALVES + B_STAGE_HALVES)          // 18432
#define SMEM_GEMM_BYTES (NSTAGE * STAGE_HALVES * 2)               // 110592

// ---------------- scratch (no runtime allocation allowed) ----------------
__device__ __align__(16) __half g_wq[(size_t)N_DIM * K_DIM];   // 32 MB
__device__ __align__(16) __half g_xh[(size_t)M_DIM * K_DIM];   // 64 MB
__device__ float g_partial[8192];
__device__ float g_scale;   // c = clip(round(gamma'), -1, 1), in {0, 1}

// ---------------- phase 1: fused prep (8 floats per thread) ----------------
// blocks [0, 8192):      W pass — q-extract to g_wq (fp16) + per-block sum|W|
// blocks [8192, 24576):  x fp32 -> fp16 convert
__global__ void prep_all_kernel(const float* __restrict__ w, const float* __restrict__ x) {
    const int t = threadIdx.x;
    if (blockIdx.x < 8192) {
        __shared__ float swarp[8];
        const float4* w4 = reinterpret_cast<const float4*>(w) + (size_t)blockIdx.x * 512;
        __half2* dst = reinterpret_cast<__half2*>(g_wq) + (size_t)blockIdx.x * 1024;

        float acc = 0.f;
        #pragma unroll
        for (int h = 0; h < 2; h++) {
            int idx = t + h * 256;            // float4 index within block chunk
            float4 v = w4[idx];
            float q0 = (v.x > 0.5f) ? 1.f : ((v.x < -0.5f) ? -1.f : 0.f);
            float q1 = (v.y > 0.5f) ? 1.f : ((v.y < -0.5f) ? -1.f : 0.f);
            float q2 = (v.z > 0.5f) ? 1.f : ((v.z < -0.5f) ? -1.f : 0.f);
            float q3 = (v.w > 0.5f) ? 1.f : ((v.w < -0.5f) ? -1.f : 0.f);
            dst[2 * idx]     = __floats2half2_rn(q0, q1);
            dst[2 * idx + 1] = __floats2half2_rn(q2, q3);
            acc += fabsf(v.x) + fabsf(v.y) + fabsf(v.z) + fabsf(v.w);
        }
        // warp-shuffle reduce
        #pragma unroll
        for (int off = 16; off > 0; off >>= 1)
            acc += __shfl_down_sync(0xFFFFFFFFu, acc, off);
        if ((t & 31) == 0) swarp[t >> 5] = acc;
        __syncthreads();
        if (t < 8) {
            float v = swarp[t];
            #pragma unroll
            for (int off = 4; off > 0; off >>= 1)
                v += __shfl_down_sync(0x000000FFu, v, off);
            if (t == 0) g_partial[blockIdx.x] = v;
        }
    } else {
        const size_t blk = blockIdx.x - 8192;
        const float4* x4 = reinterpret_cast<const float4*>(x) + blk * 512;
        __half2* dst = reinterpret_cast<__half2*>(g_xh) + blk * 1024;
        #pragma unroll
        for (int h = 0; h < 2; h++) {
            int idx = t + h * 256;
            float4 v = x4[idx];
            dst[2 * idx]     = __floats2half2_rn(v.x, v.y);
            dst[2 * idx + 1] = __floats2half2_rn(v.z, v.w);
        }
    }
}

// ---------------- phase 2: finalize gamma -> scale c ----------------
__global__ void finalize_gamma_kernel() {
    __shared__ float sred[1024];
    int t = threadIdx.x;
    float acc = 0.f;
    #pragma unroll
    for (int k = 0; k < 8; k++) acc += g_partial[t + k * 1024];
    sred[t] = acc;
    __syncthreads();
    for (int s = 512; s > 0; s >>= 1) {
        if (t < s) sred[t] += sred[t + s];
        __syncthreads();
    }
    if (t == 0) {
        float mean = sred[0] / 16777216.0f;
        float gamma = 1.0f / (mean + 1e-7f);
        // wq = clip(round(gamma * q), -1, 1) = q * c with c = min(round(gamma), 1)
        // (gamma > 0 always; rintf = round half-to-even matches jnp.round)
        g_scale = fminf(rintf(gamma), 1.0f);
    }
}

// ---------------- phase 3: conditional rescale of g_wq ----------------
// For typical inputs c == 1 and this exits immediately; correct for any input.
__global__ void fix_scale_kernel() {
    const float c = g_scale;
    if (c == 1.0f) return;
    const __half2 ch = __floats2half2_rn(c, c);
    __half2* p = reinterpret_cast<__half2*>(g_wq);
    const size_t n = (size_t)N_DIM * K_DIM / 2;
    for (size_t i = (size_t)blockIdx.x * blockDim.x + threadIdx.x; i < n;
         i += (size_t)gridDim.x * blockDim.x)
        p[i] = __hmul2(p[i], ch);
}

// ---------------- GEMM helpers ----------------
__device__ __forceinline__ uint32_t smem_u32(const void* p) {
    return static_cast<uint32_t>(__cvta_generic_to_shared(p));
}
__device__ __forceinline__ void cp_async16(uint32_t dst, const void* src) {
    asm volatile("cp.async.cg.shared.global [%0], [%1], 16;\n" :: "r"(dst), "l"(src) : "memory");
}
__device__ __forceinline__ void ldm_x4(uint32_t addr, uint32_t& r0, uint32_t& r1, uint32_t& r2, uint32_t& r3) {
    asm volatile("ldmatrix.sync.aligned.m8n8.x4.shared.b16 {%0,%1,%2,%3}, [%4];"
                 : "=r"(r0), "=r"(r1), "=r"(r2), "=r"(r3) : "r"(addr));
}
__device__ __forceinline__ void mma16816(float* c, const uint32_t* a, uint32_t b0, uint32_t b1) {
    asm volatile("mma.sync.aligned.m16n8k16.row.col.f32.f16.f16.f32 "
                 "{%0,%1,%2,%3}, {%4,%5,%6,%7}, {%8,%9}, {%0,%1,%2,%3};"
                 : "+f"(c[0]), "+f"(c[1]), "+f"(c[2]), "+f"(c[3])
                 : "r"(a[0]), "r"(a[1]), "r"(a[2]), "r"(a[3]), "r"(b0), "r"(b1));
}

// one stage: A tile 128x64 + B tile 128x64 (fp16, 16B chunks), 256 threads
__device__ __forceinline__ void load_stage(__half* Asm, __half* Bsm,
                                           const __half* Ag, const __half* Bg,
                                           int kbase, int tid) {
    #pragma unroll
    for (int j = 0; j < 4; j++) {
        int c = tid + j * 256;
        int row = c >> 3, col = (c & 7) * 8;
        cp_async16(smem_u32(Asm + row * LDS + col), Ag + (size_t)row * K_DIM + kbase + col);
    }
    #pragma unroll
    for (int j = 0; j < 4; j++) {
        int c = tid + j * 256;
        int row = c >> 3, col = (c & 7) * 8;
        cp_async16(smem_u32(Bsm + row * LDS + col), Bg + (size_t)row * K_DIM + kbase + col);
    }
    asm volatile("cp.async.commit_group;\n" ::: "memory");
}

// ---------------- phase 4: fp16 tensor-core GEMM, out = Xh @ Wq^T ----------------
__global__ void __launch_bounds__(256, 2) gemm_kernel(float* __restrict__ out) {
    extern __shared__ __half smem[];
    __half* As[NSTAGE];
    __half* Bs[NSTAGE];
    #pragma unroll
    for (int s = 0; s < NSTAGE; s++) {
        As[s] = smem + s * STAGE_HALVES;
        Bs[s] = As[s] + A_STAGE_HALVES;
    }

    const int tid  = threadIdx.x;
    const int lane = tid & 31;
    const int warp = tid >> 5;
    const int wm = (warp & 1) * 64;   // warp tile 64x32
    const int wn = (warp >> 1) * 32;
    const int m0 = blockIdx.y * BM;
    const int n0 = blockIdx.x * BN;

    const __half* Ag = g_xh + (size_t)m0 * K_DIM;
    const __half* Bg = g_wq + (size_t)n0 * K_DIM;

    float acc[4][4][4];
    #pragma unroll
    for (int a = 0; a < 4; a++)
        #pragma unroll
        for (int b = 0; b < 4; b++)
            #pragma unroll
            for (int c = 0; c < 4; c++) acc[a][b][c] = 0.f;

    // prologue: fill NSTAGE-1 stages
    #pragma unroll
    for (int s = 0; s < NSTAGE - 1; s++)
        load_stage(As[s], Bs[s], Ag, Bg, s * BK, tid);

    const int NT = K_DIM / BK;   // 64
    const int arow = (lane & 15);
    const int acol = (lane >> 4) << 3;

    int sidx = 0;
    for (int kt = 0; kt < NT; ++kt) {
        asm volatile("cp.async.wait_group %0;\n" :: "n"(NSTAGE - 2) : "memory");
        __syncthreads();

        const __half* Ab = As[sidx];
        const __half* Bb = Bs[sidx];

        #pragma unroll
        for (int kk = 0; kk < BK; kk += 16) {
            uint32_t a[4][4], b[2][4];
            #pragma unroll
            for (int im = 0; im < 4; im++) {
                uint32_t addr = smem_u32(&Ab[(wm + im * 16 + arow) * LDS + kk + acol]);
                ldm_x4(addr, a[im][0], a[im][1], a[im][2], a[im][3]);
            }
            #pragma unroll
            for (int ib = 0; ib < 2; ib++) {
                uint32_t addr = smem_u32(&Bb[(wn + ib * 16 + arow) * LDS + kk + acol]);
                ldm_x4(addr, b[ib][0], b[ib][1], b[ib][2], b[ib][3]);
            }
            #pragma unroll
            for (int im = 0; im < 4; im++)
                #pragma unroll
                for (int in = 0; in < 4; in++)
                    mma16816(acc[im][in], a[im], b[in >> 1][in & 1], b[in >> 1][(in & 1) + 2]);
        }

        // prefetch stage kt+NSTAGE-1 (buffer freed at kt-1). When past the end,
        // commit an EMPTY group so the wait_group(NSTAGE-2) invariant — "the
        // group for the buffer being consumed is never the newest pending
        // group" — holds through the drain iterations (race fix, R15).
        if (kt + NSTAGE - 1 < NT) {
            int ps = sidx + (NSTAGE - 1);
            if (ps >= NSTAGE) ps -= NSTAGE;
            load_stage(As[ps], Bs[ps], Ag, Bg, (kt + NSTAGE - 1) * BK, tid);
        } else {
            asm volatile("cp.async.commit_group;\n" ::: "memory");
        }
        if (++sidx == NSTAGE) sidx = 0;
    }

    // epilogue: fp32 streaming stores (__stcs — don't evict B tiles from L2)
    #pragma unroll
    for (int im = 0; im < 4; im++) {
        int r = m0 + wm + im * 16 + (lane >> 2);
        #pragma unroll
        for (int in = 0; in < 4; in++) {
            int c = n0 + wn + in * 8 + (lane & 3) * 2;
            __stcs(reinterpret_cast<float2*>(&out[(size_t)r * N_DIM + c]),
                   make_float2(acc[im][in][0], acc[im][in][1]));
            __stcs(reinterpret_cast<float2*>(&out[(size_t)(r + 8) * N_DIM + c]),
                   make_float2(acc[im][in][2], acc[im][in][3]));
        }
    }
}

// ---------------- launch ----------------
extern "C" void kernel_launch(void* const* d_in, const int* in_sizes, int n_in,
                              void* d_out, int out_size) {
    const float* x = (const float*)d_in[0];   // 4*2048*4096 fp32
    const float* w = (const float*)d_in[1];   // 4096*4096 fp32
    float* out = (float*)d_out;               // 4*2048*4096 fp32

    cudaFuncSetAttribute(gemm_kernel,
                         cudaFuncAttributeMaxDynamicSharedMemorySize, SMEM_GEMM_BYTES);

    prep_all_kernel<<<24576, 256>>>(w, x);       // launch 0: q-extract + |W| partials + x convert
    finalize_gamma_kernel<<<1, 1024>>>();        // launch 1: gamma -> c
    fix_scale_kernel<<<2048, 256>>>();           // launch 2: no-op when c == 1
    gemm_kernel<<<dim3(N_DIM / BN, M_DIM / BM), 256, SMEM_GEMM_BYTES>>>(out);  // launch 3
}